// round 11
// baseline (speedup 1.0000x reference)
#include <cuda_runtime.h>
#include <cstdint>

#define FIN   256
#define FOUT  256
#define BATCH 65536
#define BM    64          // batch rows per tile
#define HN    128         // output channels per CTA (half of FOUT)
#define WSTRIDE 272       // padded smem row stride (bytes) -> conflict-free frag loads
#define CSTR  128         // codes row stride (bytes)
#define SMEM_B (HN*WSTRIDE + BM*WSTRIDE)   // 52224 bytes -> 3 CTAs/SM

// ---------------- device scratch ----------------
__device__ unsigned int g_bmax[64];             // per-block |w| max bits
__device__ float        g_params[2];            // [0]=scale_w, [1]=scale_w/15
__device__ int          g_csum [FOUT];
__device__ int          g_csum2[FOUT];
__device__ __align__(16) signed char g_wq[FOUT*FIN];   // quantized weights s8
__device__ signed char  g_codes[(size_t)BATCH*FOUT];   // 16MB int8 acc codes

// ---------------- helpers ----------------
__device__ __forceinline__ void mma_u8s8(int* c, const unsigned* a, unsigned b0, unsigned b1) {
    asm volatile(
        "mma.sync.aligned.m16n8k32.row.col.s32.u8.s8.s32 "
        "{%0,%1,%2,%3},{%4,%5,%6,%7},{%8,%9},{%0,%1,%2,%3};"
        : "+r"(c[0]), "+r"(c[1]), "+r"(c[2]), "+r"(c[3])
        : "r"(a[0]), "r"(a[1]), "r"(a[2]), "r"(a[3]), "r"(b0), "r"(b1));
}
__device__ __forceinline__ unsigned qact(float v) {
    return (unsigned)(int)rintf(fminf(fmaxf(v, 0.0f), 1.0f) * 15.0f);
}
// exact round-half-even(p/1792), p integer in [-13440, 13440]
__device__ __forceinline__ int rne1792(int p) {
    unsigned pp = (unsigned)(p + 15232);          // p + 896 + 8*1792 >= 0
    unsigned q = pp / 1792u;                      // umulhi + shift
    unsigned rem = pp - q * 1792u;
    int r = (int)q - 8;
    if (rem == 0u) r -= (r & 1);                  // tie -> even
    return r;
}

// ---------------- kernel A1: per-block max|W| (+ stat zeroing by block 0) ----------------
__global__ void kA1(const float* __restrict__ w) {
    if (blockIdx.x == 0) {                        // zero accumulators before kB
        g_csum [threadIdx.x] = 0;
        g_csum2[threadIdx.x] = 0;
    }
    int j = blockIdx.x * 256 + threadIdx.x;       // float4 id, 16384 total
    float4 v = ((const float4*)w)[j];
    unsigned m = max(max(__float_as_uint(fabsf(v.x)), __float_as_uint(fabsf(v.y))),
                     max(__float_as_uint(fabsf(v.z)), __float_as_uint(fabsf(v.w))));
    #pragma unroll
    for (int o = 16; o; o >>= 1) m = max(m, __shfl_xor_sync(0xffffffffu, m, o));
    __shared__ unsigned sm[8];
    if ((threadIdx.x & 31) == 0) sm[threadIdx.x >> 5] = m;
    __syncthreads();
    if (threadIdx.x == 0) {
        #pragma unroll
        for (int i = 1; i < 8; i++) m = max(m, sm[i]);
        g_bmax[blockIdx.x] = m;
    }
}

// ---------------- kernel A2: reduce max, quantize weights ----------------
__global__ void kA2(const float* __restrict__ w) {
    __shared__ unsigned sm[64];
    __shared__ float sscale;
    int tid = threadIdx.x;
    if (tid < 64) sm[tid] = g_bmax[tid];
    __syncthreads();
    if (tid == 0) {
        unsigned m = sm[0];
        #pragma unroll
        for (int i = 1; i < 64; i++) m = max(m, sm[i]);
        float scale = __fdiv_rn(__uint_as_float(m), 7.0f);
        sscale = scale;
        if (blockIdx.x == 0) {
            g_params[0] = scale;
            g_params[1] = __fdiv_rn(scale, 15.0f);
        }
    }
    __syncthreads();
    float scale = sscale;
    int j = blockIdx.x * 256 + tid;               // float4 id
    float4 v = ((const float4*)w)[j];
    char4 q;
    q.x = (signed char)(int)rintf(fminf(fmaxf(__fdiv_rn(v.x, scale), -7.0f), 7.0f));
    q.y = (signed char)(int)rintf(fminf(fmaxf(__fdiv_rn(v.y, scale), -7.0f), 7.0f));
    q.z = (signed char)(int)rintf(fminf(fmaxf(__fdiv_rn(v.z, scale), -7.0f), 7.0f));
    q.w = (signed char)(int)rintf(fminf(fmaxf(__fdiv_rn(v.w, scale), -7.0f), 7.0f));
    ((char4*)g_wq)[j] = q;
}

// ---------------- kernel B: (row-tile, channel-half) CTAs; 3 CTAs/SM ----------------
__global__ void __launch_bounds__(256, 3) kB(const float* __restrict__ x) {
    extern __shared__ unsigned char sm[];
    unsigned char* w_s = sm;                  // [HN][WSTRIDE]
    unsigned char* x_s = sm + HN * WSTRIDE;   // [BM][WSTRIDE], reused as codes [BM][CSTR]
    signed char*   codes = (signed char*)x_s;

    const int tid = threadIdx.x;
    const int tile = blockIdx.x >> 1;
    const int half = blockIdx.x & 1;

    // --- load this half's quantized weights (32KB, L2-hot) ---
    {
        const int4* wg = (const int4*)(g_wq + half * HN * FIN);
        #pragma unroll
        for (int i = 0; i < 8; i++) {
            int j = tid + i * 256;          // int4 idx 0..2047
            int row = j >> 4, col = j & 15;
            *(int4*)(w_s + row * WSTRIDE + col * 16) = wg[j];
        }
    }
    // --- load + quantize activations ---
    {
        const float4* xg = (const float4*)(x + (size_t)tile * BM * FIN);
        #pragma unroll
        for (int i = 0; i < 16; i++) {
            int j = tid + i * 256;          // float4 idx 0..4095
            float4 v = xg[j];
            int row = j >> 6, c4 = j & 63;
            unsigned p = qact(v.x) | (qact(v.y) << 8) | (qact(v.z) << 16) | (qact(v.w) << 24);
            *(unsigned*)(x_s + row * WSTRIDE + c4 * 4) = p;
        }
    }
    __syncthreads();

    const int warp = tid >> 5, lane = tid & 31;
    const int g = lane >> 2, tq = lane & 3;
    const int m0 = (warp & 3) * 16;     // m16 fragment base row
    const int n0 = (warp >> 2) * 64;    // 64 local channels per warp-half

    // --- preload all A fragments for this warp (2 tiles x 4 ksteps) ---
    unsigned a[8][4];
    #pragma unroll
    for (int tk = 0; tk < 8; tk++) {
        int koff = tk * 32;
        a[tk][0] = *(const unsigned*)(x_s + (m0 + g    ) * WSTRIDE + koff +      tq * 4);
        a[tk][1] = *(const unsigned*)(x_s + (m0 + g + 8) * WSTRIDE + koff +      tq * 4);
        a[tk][2] = *(const unsigned*)(x_s + (m0 + g    ) * WSTRIDE + koff + 16 + tq * 4);
        a[tk][3] = *(const unsigned*)(x_s + (m0 + g + 8) * WSTRIDE + koff + 16 + tq * 4);
    }
    __syncthreads();   // x_s region now free -> code staging

    // --- main MMA loop: 8 n-fragments; two crossbar-tile chains interleaved ---
    #pragma unroll 2
    for (int nf = 0; nf < 8; nf++) {
        const int nrow = n0 + nf * 8 + g;        // local channel row in w_s
        const unsigned char* wrow = w_s + nrow * WSTRIDE;
        int c0[4] = {0, 0, 0, 0};                // crossbar tile 0 chain
        int c1[4] = {0, 0, 0, 0};                // crossbar tile 1 chain
        #pragma unroll
        for (int k = 0; k < 4; k++) {
            int k0 = k * 32, k1 = 128 + k * 32;
            unsigned b00 = *(const unsigned*)(wrow + k0 +      tq * 4);
            unsigned b01 = *(const unsigned*)(wrow + k0 + 16 + tq * 4);
            unsigned b10 = *(const unsigned*)(wrow + k1 +      tq * 4);
            unsigned b11 = *(const unsigned*)(wrow + k1 + 16 + tq * 4);
            mma_u8s8(c0, a[k],     b00, b01);    // independent chains
            mma_u8s8(c1, a[4 + k], b10, b11);
        }
        int rr[4];
        #pragma unroll
        for (int e = 0; e < 4; e++) rr[e] = rne1792(c0[e]) + rne1792(c1[e]);

        int col = n0 + nf * 8 + tq * 2;          // local channel column
        unsigned short p01 = (unsigned short)((rr[0] & 0xFF) | ((rr[1] & 0xFF) << 8));
        unsigned short p23 = (unsigned short)((rr[2] & 0xFF) | ((rr[3] & 0xFF) << 8));
        *(unsigned short*)(codes + (m0 + g    ) * CSTR + col) = p01;
        *(unsigned short*)(codes + (m0 + g + 8) * CSTR + col) = p23;
    }
    __syncthreads();

    // --- per-channel integer stats (128 local channels) ---
    if (tid < HN) {
        int s = 0, s2 = 0;
        #pragma unroll
        for (int r = 0; r < BM; r++) {
            int v = (int)codes[r * CSTR + tid];
            s += v; s2 += v * v;
        }
        atomicAdd(&g_csum [half * HN + tid], s);
        atomicAdd(&g_csum2[half * HN + tid], s2);
    }

    // --- coalesced code writeout (128B per row into 256B-stride rows) ---
    {
        signed char* dstb = g_codes + (size_t)tile * BM * FOUT + half * HN;
        #pragma unroll
        for (int i = 0; i < 2; i++) {
            int j = tid + i * 256;               // int4 id 0..511
            int row = j >> 3, c16 = (j & 7) * 16;
            *(int4*)(dstb + row * FOUT + c16) = *(const int4*)(codes + row * CSTR + c16);
        }
    }
}

// ---------------- kernel D: register BN params, char4, high CTA count ----------------
__global__ void __launch_bounds__(256) kD(const float* __restrict__ gamma,
                                          const float* __restrict__ beta,
                                          float* __restrict__ out) {
    __shared__ float4 bn[FOUT];                   // mu, rs, gamma, beta
    __shared__ float lut[16];                     // q -> __fdiv_rn(q, 15)
    const int t = threadIdx.x;
    {
        float sw15 = g_params[1];
        double C  = 1792.0 * (double)sw15;
        double s  = (double)g_csum[t];
        double s2 = (double)g_csum2[t];
        double mu = C * s / 65536.0;
        double m2 = C * C * s2 / 65536.0;
        double var = m2 - mu * mu;
        float tt = (float)var + 1e-5f;
        float rs = (float)(1.0 / sqrt((double)tt));
        bn[t] = make_float4((float)mu, rs, gamma[t], beta[t]);
    }
    if (t < 16) lut[t] = __fdiv_rn((float)t, 15.0f);
    __syncthreads();

    // channel group is CONSTANT per thread: (i4 & 63) == (t & 63) since
    // block stride 2048 and iteration stride 256 are both multiples of 64
    const int o = (t & 63) * 4;
    const float4 b0 = bn[o + 0], b1 = bn[o + 1], b2 = bn[o + 2], b3 = bn[o + 3];
    const float sw15 = g_params[1];

    size_t base = (size_t)blockIdx.x * 2048 + t;  // char4 indices, 2048 blocks
    #pragma unroll
    for (int i = 0; i < 8; i++) {
        size_t i4 = base + (size_t)i * 256;
        char4 cc = ((const char4*)g_codes)[i4];
        float4 r;
        {
            float acc = __fmul_rn((float)((int)cc.x * 1792), sw15);
            float y = ((acc - b0.x) * b0.y) * b0.z + b0.w;
            r.x = lut[(int)rintf(fminf(fmaxf(y, 0.0f), 1.0f) * 15.0f)];
        }
        {
            float acc = __fmul_rn((float)((int)cc.y * 1792), sw15);
            float y = ((acc - b1.x) * b1.y) * b1.z + b1.w;
            r.y = lut[(int)rintf(fminf(fmaxf(y, 0.0f), 1.0f) * 15.0f)];
        }
        {
            float acc = __fmul_rn((float)((int)cc.z * 1792), sw15);
            float y = ((acc - b2.x) * b2.y) * b2.z + b2.w;
            r.z = lut[(int)rintf(fminf(fmaxf(y, 0.0f), 1.0f) * 15.0f)];
        }
        {
            float acc = __fmul_rn((float)((int)cc.w * 1792), sw15);
            float y = ((acc - b3.x) * b3.y) * b3.z + b3.w;
            r.w = lut[(int)rintf(fminf(fmaxf(y, 0.0f), 1.0f) * 15.0f)];
        }
        ((float4*)out)[i4] = r;
    }
}

// ---------------- host launch ----------------
extern "C" void kernel_launch(void* const* d_in, const int* in_sizes, int n_in,
                              void* d_out, int out_size) {
    const float* x     = (const float*)d_in[0];
    const float* w     = (const float*)d_in[1];
    const float* gamma = (const float*)d_in[2];
    const float* beta  = (const float*)d_in[3];
    float* out = (float*)d_out;

    cudaFuncSetAttribute(kB, cudaFuncAttributeMaxDynamicSharedMemorySize, SMEM_B);

    kA1<<<64, 256>>>(w);
    kA2<<<64, 256>>>(w);
    kB <<<2 * (BATCH / BM), 256, SMEM_B>>>(x);    // 2048 CTAs: (tile, half)
    kD <<<2048, 256>>>(gamma, beta, out);         // 2048 * 2048 char4 = 4194304
    (void)in_sizes; (void)n_in; (void)out_size;
}

// round 12
// speedup vs baseline: 1.1298x; 1.1298x over previous
#include <cuda_runtime.h>
#include <cstdint>

#define FIN   256
#define FOUT  256
#define BATCH 65536
#define BM    64          // batch rows per tile
#define HN    128         // output channels per CTA (half of FOUT)
#define WSTRIDE 272       // padded smem row stride (bytes) -> conflict-free frag loads
#define CSTR  128         // codes row stride (bytes)
#define SMEM_B (HN*WSTRIDE + BM*WSTRIDE)   // 52224 bytes -> 3 CTAs/SM

// ---------------- device scratch ----------------
__device__ unsigned int g_bmax[64];             // per-block |w| max bits
__device__ float        g_params[2];            // [0]=scale_w, [1]=scale_w/15
__device__ int          g_csum [FOUT];
__device__ int          g_csum2[FOUT];
__device__ __align__(16) signed char g_wq[FOUT*FIN];   // quantized weights s8
__device__ signed char  g_codes[(size_t)BATCH*FOUT];   // 16MB int8 acc codes
__device__ float4       g_bn[FOUT];             // mu, rs, gamma, beta
__device__ float        g_lut[16];              // q -> __fdiv_rn(q,15)

// ---------------- helpers ----------------
__device__ __forceinline__ void mma_u8s8(int* c, const unsigned* a, unsigned b0, unsigned b1) {
    asm volatile(
        "mma.sync.aligned.m16n8k32.row.col.s32.u8.s8.s32 "
        "{%0,%1,%2,%3},{%4,%5,%6,%7},{%8,%9},{%0,%1,%2,%3};"
        : "+r"(c[0]), "+r"(c[1]), "+r"(c[2]), "+r"(c[3])
        : "r"(a[0]), "r"(a[1]), "r"(a[2]), "r"(a[3]), "r"(b0), "r"(b1));
}
__device__ __forceinline__ unsigned qact(float v) {
    return (unsigned)(int)rintf(fminf(fmaxf(v, 0.0f), 1.0f) * 15.0f);
}
// exact round-half-even(p/1792), p integer in [-13440, 13440]
__device__ __forceinline__ int rne1792(int p) {
    unsigned pp = (unsigned)(p + 15232);          // p + 896 + 8*1792 >= 0
    unsigned q = pp / 1792u;                      // umulhi + shift
    unsigned rem = pp - q * 1792u;
    int r = (int)q - 8;
    if (rem == 0u) r -= (r & 1);                  // tie -> even
    return r;
}

// ---------------- kernel A1: per-block max|W| (+ stat zeroing by block 0) ----------------
__global__ void kA1(const float* __restrict__ w) {
    if (blockIdx.x == 0) {                        // zero accumulators before kB
        g_csum [threadIdx.x] = 0;
        g_csum2[threadIdx.x] = 0;
    }
    int j = blockIdx.x * 256 + threadIdx.x;       // float4 id, 16384 total
    float4 v = ((const float4*)w)[j];
    unsigned m = max(max(__float_as_uint(fabsf(v.x)), __float_as_uint(fabsf(v.y))),
                     max(__float_as_uint(fabsf(v.z)), __float_as_uint(fabsf(v.w))));
    #pragma unroll
    for (int o = 16; o; o >>= 1) m = max(m, __shfl_xor_sync(0xffffffffu, m, o));
    __shared__ unsigned sm[8];
    if ((threadIdx.x & 31) == 0) sm[threadIdx.x >> 5] = m;
    __syncthreads();
    if (threadIdx.x == 0) {
        #pragma unroll
        for (int i = 1; i < 8; i++) m = max(m, sm[i]);
        g_bmax[blockIdx.x] = m;
    }
}

// ---------------- kernel A2: reduce max, quantize weights ----------------
__global__ void kA2(const float* __restrict__ w) {
    __shared__ unsigned sm[64];
    __shared__ float sscale;
    int tid = threadIdx.x;
    if (tid < 64) sm[tid] = g_bmax[tid];
    __syncthreads();
    if (tid == 0) {
        unsigned m = sm[0];
        #pragma unroll
        for (int i = 1; i < 64; i++) m = max(m, sm[i]);
        float scale = __fdiv_rn(__uint_as_float(m), 7.0f);
        sscale = scale;
        if (blockIdx.x == 0) {
            g_params[0] = scale;
            g_params[1] = __fdiv_rn(scale, 15.0f);
        }
    }
    __syncthreads();
    float scale = sscale;
    int j = blockIdx.x * 256 + tid;               // float4 id
    float4 v = ((const float4*)w)[j];
    char4 q;
    q.x = (signed char)(int)rintf(fminf(fmaxf(__fdiv_rn(v.x, scale), -7.0f), 7.0f));
    q.y = (signed char)(int)rintf(fminf(fmaxf(__fdiv_rn(v.y, scale), -7.0f), 7.0f));
    q.z = (signed char)(int)rintf(fminf(fmaxf(__fdiv_rn(v.z, scale), -7.0f), 7.0f));
    q.w = (signed char)(int)rintf(fminf(fmaxf(__fdiv_rn(v.w, scale), -7.0f), 7.0f));
    ((char4*)g_wq)[j] = q;
}

// ---------------- kernel B: (row-tile, channel-half) CTAs; 3 CTAs/SM ----------------
__global__ void __launch_bounds__(256, 3) kB(const float* __restrict__ x) {
    extern __shared__ unsigned char sm[];
    unsigned char* w_s = sm;                  // [HN][WSTRIDE]
    unsigned char* x_s = sm + HN * WSTRIDE;   // [BM][WSTRIDE], reused as codes [BM][CSTR]
    signed char*   codes = (signed char*)x_s;

    const int tid = threadIdx.x;
    const int tile = blockIdx.x >> 1;
    const int half = blockIdx.x & 1;

    // --- load this half's quantized weights (32KB, L2-hot) ---
    {
        const int4* wg = (const int4*)(g_wq + half * HN * FIN);
        #pragma unroll
        for (int i = 0; i < 8; i++) {
            int j = tid + i * 256;          // int4 idx 0..2047
            int row = j >> 4, col = j & 15;
            *(int4*)(w_s + row * WSTRIDE + col * 16) = wg[j];
        }
    }
    // --- load + quantize activations ---
    {
        const float4* xg = (const float4*)(x + (size_t)tile * BM * FIN);
        #pragma unroll
        for (int i = 0; i < 16; i++) {
            int j = tid + i * 256;          // float4 idx 0..4095
            float4 v = xg[j];
            int row = j >> 6, c4 = j & 63;
            unsigned p = qact(v.x) | (qact(v.y) << 8) | (qact(v.z) << 16) | (qact(v.w) << 24);
            *(unsigned*)(x_s + row * WSTRIDE + c4 * 4) = p;
        }
    }
    __syncthreads();

    const int warp = tid >> 5, lane = tid & 31;
    const int g = lane >> 2, tq = lane & 3;
    const int m0 = (warp & 3) * 16;     // m16 fragment base row
    const int n0 = (warp >> 2) * 64;    // 64 local channels per warp-half

    // --- preload all A fragments for this warp (2 tiles x 4 ksteps) ---
    unsigned a[8][4];
    #pragma unroll
    for (int tk = 0; tk < 8; tk++) {
        int koff = tk * 32;
        a[tk][0] = *(const unsigned*)(x_s + (m0 + g    ) * WSTRIDE + koff +      tq * 4);
        a[tk][1] = *(const unsigned*)(x_s + (m0 + g + 8) * WSTRIDE + koff +      tq * 4);
        a[tk][2] = *(const unsigned*)(x_s + (m0 + g    ) * WSTRIDE + koff + 16 + tq * 4);
        a[tk][3] = *(const unsigned*)(x_s + (m0 + g + 8) * WSTRIDE + koff + 16 + tq * 4);
    }
    __syncthreads();   // x_s region now free -> code staging

    // --- main MMA loop: 8 n-fragments; two crossbar-tile chains interleaved ---
    #pragma unroll 2
    for (int nf = 0; nf < 8; nf++) {
        const int nrow = n0 + nf * 8 + g;        // local channel row in w_s
        const unsigned char* wrow = w_s + nrow * WSTRIDE;
        int c0[4] = {0, 0, 0, 0};                // crossbar tile 0 chain
        int c1[4] = {0, 0, 0, 0};                // crossbar tile 1 chain
        #pragma unroll
        for (int k = 0; k < 4; k++) {
            int k0 = k * 32, k1 = 128 + k * 32;
            unsigned b00 = *(const unsigned*)(wrow + k0 +      tq * 4);
            unsigned b01 = *(const unsigned*)(wrow + k0 + 16 + tq * 4);
            unsigned b10 = *(const unsigned*)(wrow + k1 +      tq * 4);
            unsigned b11 = *(const unsigned*)(wrow + k1 + 16 + tq * 4);
            mma_u8s8(c0, a[k],     b00, b01);    // independent chains
            mma_u8s8(c1, a[4 + k], b10, b11);
        }
        int rr[4];
        #pragma unroll
        for (int e = 0; e < 4; e++) rr[e] = rne1792(c0[e]) + rne1792(c1[e]);

        int col = n0 + nf * 8 + tq * 2;          // local channel column
        unsigned short p01 = (unsigned short)((rr[0] & 0xFF) | ((rr[1] & 0xFF) << 8));
        unsigned short p23 = (unsigned short)((rr[2] & 0xFF) | ((rr[3] & 0xFF) << 8));
        *(unsigned short*)(codes + (m0 + g    ) * CSTR + col) = p01;
        *(unsigned short*)(codes + (m0 + g + 8) * CSTR + col) = p23;
    }
    __syncthreads();

    // --- per-channel integer stats (128 local channels) ---
    if (tid < HN) {
        int s = 0, s2 = 0;
        #pragma unroll
        for (int r = 0; r < BM; r++) {
            int v = (int)codes[r * CSTR + tid];
            s += v; s2 += v * v;
        }
        atomicAdd(&g_csum [half * HN + tid], s);
        atomicAdd(&g_csum2[half * HN + tid], s2);
    }

    // --- coalesced code writeout (128B per row into 256B-stride rows) ---
    {
        signed char* dstb = g_codes + (size_t)tile * BM * FOUT + half * HN;
        #pragma unroll
        for (int i = 0; i < 2; i++) {
            int j = tid + i * 256;               // int4 id 0..511
            int row = j >> 3, c16 = (j & 7) * 16;
            *(int4*)(dstb + row * FOUT + c16) = *(const int4*)(codes + row * CSTR + c16);
        }
    }
}

// ---------------- kernel C: finalize BN stats once (tiny) ----------------
__global__ void kC(const float* __restrict__ gamma, const float* __restrict__ beta) {
    int o = threadIdx.x;
    float sw15 = g_params[1];
    double C  = 1792.0 * (double)sw15;
    double s  = (double)g_csum[o];
    double s2 = (double)g_csum2[o];
    double mu = C * s / 65536.0;
    double m2 = C * C * s2 / 65536.0;
    double var = m2 - mu * mu;
    float tt = (float)var + 1e-5f;
    float rs = (float)(1.0 / sqrt((double)tt));
    g_bn[o] = make_float4((float)mu, rs, gamma[o], beta[o]);
    if (o < 16) g_lut[o] = __fdiv_rn((float)o, 15.0f);
}

// ---------------- kernel D: thin prologue, fully unrolled latency-hiding body ----------------
__global__ void __launch_bounds__(256) kD(float* __restrict__ out) {
    __shared__ float lut[16];
    const int t = threadIdx.x;
    if (t < 16) lut[t] = g_lut[t];
    // channel group constant per thread: block stride 4096 and iter stride 256
    // are multiples of 64 -> (i4 & 63) == (t & 63)
    const int o = (t & 63) * 4;
    const float4 b0 = g_bn[o + 0], b1 = g_bn[o + 1], b2 = g_bn[o + 2], b3 = g_bn[o + 3];
    const float sw15 = g_params[1];
    __syncthreads();

    size_t base = (size_t)blockIdx.x * 4096 + t;  // char4 indices, 1024 blocks
    #pragma unroll
    for (int i = 0; i < 16; i++) {
        size_t i4 = base + (size_t)i * 256;
        char4 cc = ((const char4*)g_codes)[i4];
        float4 r;
        {
            float acc = __fmul_rn((float)((int)cc.x * 1792), sw15);
            float y = ((acc - b0.x) * b0.y) * b0.z + b0.w;
            r.x = lut[(int)rintf(fminf(fmaxf(y, 0.0f), 1.0f) * 15.0f)];
        }
        {
            float acc = __fmul_rn((float)((int)cc.y * 1792), sw15);
            float y = ((acc - b1.x) * b1.y) * b1.z + b1.w;
            r.y = lut[(int)rintf(fminf(fmaxf(y, 0.0f), 1.0f) * 15.0f)];
        }
        {
            float acc = __fmul_rn((float)((int)cc.z * 1792), sw15);
            float y = ((acc - b2.x) * b2.y) * b2.z + b2.w;
            r.z = lut[(int)rintf(fminf(fmaxf(y, 0.0f), 1.0f) * 15.0f)];
        }
        {
            float acc = __fmul_rn((float)((int)cc.w * 1792), sw15);
            float y = ((acc - b3.x) * b3.y) * b3.z + b3.w;
            r.w = lut[(int)rintf(fminf(fmaxf(y, 0.0f), 1.0f) * 15.0f)];
        }
        ((float4*)out)[i4] = r;
    }
}

// ---------------- host launch ----------------
extern "C" void kernel_launch(void* const* d_in, const int* in_sizes, int n_in,
                              void* d_out, int out_size) {
    const float* x     = (const float*)d_in[0];
    const float* w     = (const float*)d_in[1];
    const float* gamma = (const float*)d_in[2];
    const float* beta  = (const float*)d_in[3];
    float* out = (float*)d_out;

    cudaFuncSetAttribute(kB, cudaFuncAttributeMaxDynamicSharedMemorySize, SMEM_B);

    kA1<<<64, 256>>>(w);
    kA2<<<64, 256>>>(w);
    kB <<<2 * (BATCH / BM), 256, SMEM_B>>>(x);    // 2048 CTAs: (tile, half)
    kC <<<1, 256>>>(gamma, beta);
    kD <<<1024, 256>>>(out);                      // 1024 * 4096 char4 = 4194304
    (void)in_sizes; (void)n_in; (void)out_size;
}

// round 13
// speedup vs baseline: 1.1547x; 1.0221x over previous
#include <cuda_runtime.h>
#include <cstdint>

#define FIN   256
#define FOUT  256
#define BATCH 65536
#define BM    64          // batch rows per tile
#define HN    128         // output channels per CTA (half of FOUT)
#define WSTRIDE 272       // padded smem row stride (bytes) -> conflict-free frag loads
#define CSTR  128         // codes row stride (bytes)
#define NB_B  (2 * (BATCH / BM))           // 2048 kB CTAs
#define SMEM_B (HN*WSTRIDE + BM*WSTRIDE)   // 52224 bytes -> 3 CTAs/SM

// ---------------- device scratch ----------------
__device__ unsigned int g_bmax[64];             // per-block |w| max bits
__device__ float        g_params[2];            // [0]=scale_w, [1]=scale_w/15
__device__ int          g_csum [FOUT];
__device__ int          g_csum2[FOUT];
__device__ unsigned int g_done;                 // kB completion counter
__device__ __align__(16) signed char g_wq[FOUT*FIN];   // quantized weights s8
__device__ signed char  g_codes[(size_t)BATCH*FOUT];   // 16MB int8 acc codes
__device__ float4       g_bn[FOUT];             // mu, rs, gamma, beta
__device__ float        g_lut[16];              // q -> __fdiv_rn(q,15)

// ---------------- helpers ----------------
__device__ __forceinline__ void mma_u8s8(int* c, const unsigned* a, unsigned b0, unsigned b1) {
    asm volatile(
        "mma.sync.aligned.m16n8k32.row.col.s32.u8.s8.s32 "
        "{%0,%1,%2,%3},{%4,%5,%6,%7},{%8,%9},{%0,%1,%2,%3};"
        : "+r"(c[0]), "+r"(c[1]), "+r"(c[2]), "+r"(c[3])
        : "r"(a[0]), "r"(a[1]), "r"(a[2]), "r"(a[3]), "r"(b0), "r"(b1));
}
__device__ __forceinline__ unsigned qact(float v) {
    return (unsigned)(int)rintf(fminf(fmaxf(v, 0.0f), 1.0f) * 15.0f);
}
// exact round-half-even(p/1792), p integer in [-13440, 13440]
__device__ __forceinline__ int rne1792(int p) {
    unsigned pp = (unsigned)(p + 15232);          // p + 896 + 8*1792 >= 0
    unsigned q = pp / 1792u;                      // umulhi + shift
    unsigned rem = pp - q * 1792u;
    int r = (int)q - 8;
    if (rem == 0u) r -= (r & 1);                  // tie -> even
    return r;
}

// ---------------- kernel A1: per-block max|W| (+ zeroing by block 0) ----------------
__global__ void kA1(const float* __restrict__ w) {
    if (blockIdx.x == 0) {                        // reset accumulators every replay
        g_csum [threadIdx.x] = 0;
        g_csum2[threadIdx.x] = 0;
        if (threadIdx.x == 0) g_done = 0u;
    }
    int j = blockIdx.x * 256 + threadIdx.x;       // float4 id, 16384 total
    float4 v = ((const float4*)w)[j];
    unsigned m = max(max(__float_as_uint(fabsf(v.x)), __float_as_uint(fabsf(v.y))),
                     max(__float_as_uint(fabsf(v.z)), __float_as_uint(fabsf(v.w))));
    #pragma unroll
    for (int o = 16; o; o >>= 1) m = max(m, __shfl_xor_sync(0xffffffffu, m, o));
    __shared__ unsigned sm[8];
    if ((threadIdx.x & 31) == 0) sm[threadIdx.x >> 5] = m;
    __syncthreads();
    if (threadIdx.x == 0) {
        #pragma unroll
        for (int i = 1; i < 8; i++) m = max(m, sm[i]);
        g_bmax[blockIdx.x] = m;
    }
}

// ---------------- kernel A2: reduce max, quantize weights ----------------
__global__ void kA2(const float* __restrict__ w) {
    __shared__ unsigned sm[64];
    __shared__ float sscale;
    int tid = threadIdx.x;
    if (tid < 64) sm[tid] = g_bmax[tid];
    __syncthreads();
    if (tid == 0) {
        unsigned m = sm[0];
        #pragma unroll
        for (int i = 1; i < 64; i++) m = max(m, sm[i]);
        float scale = __fdiv_rn(__uint_as_float(m), 7.0f);
        sscale = scale;
        if (blockIdx.x == 0) {
            g_params[0] = scale;
            g_params[1] = __fdiv_rn(scale, 15.0f);
        }
    }
    __syncthreads();
    float scale = sscale;
    int j = blockIdx.x * 256 + tid;               // float4 id
    float4 v = ((const float4*)w)[j];
    char4 q;
    q.x = (signed char)(int)rintf(fminf(fmaxf(__fdiv_rn(v.x, scale), -7.0f), 7.0f));
    q.y = (signed char)(int)rintf(fminf(fmaxf(__fdiv_rn(v.y, scale), -7.0f), 7.0f));
    q.z = (signed char)(int)rintf(fminf(fmaxf(__fdiv_rn(v.z, scale), -7.0f), 7.0f));
    q.w = (signed char)(int)rintf(fminf(fmaxf(__fdiv_rn(v.w, scale), -7.0f), 7.0f));
    ((char4*)g_wq)[j] = q;
}

// ---------------- kernel B: GEMM + stats; LAST CTA finalizes BN ----------------
__global__ void __launch_bounds__(256, 3) kB(const float* __restrict__ x,
                                             const float* __restrict__ gamma,
                                             const float* __restrict__ beta) {
    extern __shared__ unsigned char sm[];
    unsigned char* w_s = sm;                  // [HN][WSTRIDE]
    unsigned char* x_s = sm + HN * WSTRIDE;   // [BM][WSTRIDE], reused as codes [BM][CSTR]
    signed char*   codes = (signed char*)x_s;
    __shared__ int s_last;

    const int tid = threadIdx.x;
    const int tile = blockIdx.x >> 1;
    const int half = blockIdx.x & 1;

    // --- load this half's quantized weights (32KB, L2-hot) ---
    {
        const int4* wg = (const int4*)(g_wq + half * HN * FIN);
        #pragma unroll
        for (int i = 0; i < 8; i++) {
            int j = tid + i * 256;          // int4 idx 0..2047
            int row = j >> 4, col = j & 15;
            *(int4*)(w_s + row * WSTRIDE + col * 16) = wg[j];
        }
    }
    // --- load + quantize activations ---
    {
        const float4* xg = (const float4*)(x + (size_t)tile * BM * FIN);
        #pragma unroll
        for (int i = 0; i < 16; i++) {
            int j = tid + i * 256;          // float4 idx 0..4095
            float4 v = xg[j];
            int row = j >> 6, c4 = j & 63;
            unsigned p = qact(v.x) | (qact(v.y) << 8) | (qact(v.z) << 16) | (qact(v.w) << 24);
            *(unsigned*)(x_s + row * WSTRIDE + c4 * 4) = p;
        }
    }
    __syncthreads();

    const int warp = tid >> 5, lane = tid & 31;
    const int g = lane >> 2, tq = lane & 3;
    const int m0 = (warp & 3) * 16;     // m16 fragment base row
    const int n0 = (warp >> 2) * 64;    // 64 local channels per warp-half

    // --- preload all A fragments for this warp (2 tiles x 4 ksteps) ---
    unsigned a[8][4];
    #pragma unroll
    for (int tk = 0; tk < 8; tk++) {
        int koff = tk * 32;
        a[tk][0] = *(const unsigned*)(x_s + (m0 + g    ) * WSTRIDE + koff +      tq * 4);
        a[tk][1] = *(const unsigned*)(x_s + (m0 + g + 8) * WSTRIDE + koff +      tq * 4);
        a[tk][2] = *(const unsigned*)(x_s + (m0 + g    ) * WSTRIDE + koff + 16 + tq * 4);
        a[tk][3] = *(const unsigned*)(x_s + (m0 + g + 8) * WSTRIDE + koff + 16 + tq * 4);
    }
    __syncthreads();   // x_s region now free -> code staging

    // --- main MMA loop: 8 n-fragments; two crossbar-tile chains interleaved ---
    #pragma unroll 2
    for (int nf = 0; nf < 8; nf++) {
        const int nrow = n0 + nf * 8 + g;        // local channel row in w_s
        const unsigned char* wrow = w_s + nrow * WSTRIDE;
        int c0[4] = {0, 0, 0, 0};                // crossbar tile 0 chain
        int c1[4] = {0, 0, 0, 0};                // crossbar tile 1 chain
        #pragma unroll
        for (int k = 0; k < 4; k++) {
            int k0 = k * 32, k1 = 128 + k * 32;
            unsigned b00 = *(const unsigned*)(wrow + k0 +      tq * 4);
            unsigned b01 = *(const unsigned*)(wrow + k0 + 16 + tq * 4);
            unsigned b10 = *(const unsigned*)(wrow + k1 +      tq * 4);
            unsigned b11 = *(const unsigned*)(wrow + k1 + 16 + tq * 4);
            mma_u8s8(c0, a[k],     b00, b01);    // independent chains
            mma_u8s8(c1, a[4 + k], b10, b11);
        }
        int rr[4];
        #pragma unroll
        for (int e = 0; e < 4; e++) rr[e] = rne1792(c0[e]) + rne1792(c1[e]);

        int col = n0 + nf * 8 + tq * 2;          // local channel column
        unsigned short p01 = (unsigned short)((rr[0] & 0xFF) | ((rr[1] & 0xFF) << 8));
        unsigned short p23 = (unsigned short)((rr[2] & 0xFF) | ((rr[3] & 0xFF) << 8));
        *(unsigned short*)(codes + (m0 + g    ) * CSTR + col) = p01;
        *(unsigned short*)(codes + (m0 + g + 8) * CSTR + col) = p23;
    }
    __syncthreads();

    // --- per-channel integer stats (128 local channels) ---
    if (tid < HN) {
        int s = 0, s2 = 0;
        #pragma unroll
        for (int r = 0; r < BM; r++) {
            int v = (int)codes[r * CSTR + tid];
            s += v; s2 += v * v;
        }
        atomicAdd(&g_csum [half * HN + tid], s);
        atomicAdd(&g_csum2[half * HN + tid], s2);
    }

    // --- coalesced code writeout (128B per row into 256B-stride rows) ---
    {
        signed char* dstb = g_codes + (size_t)tile * BM * FOUT + half * HN;
        #pragma unroll
        for (int i = 0; i < 2; i++) {
            int j = tid + i * 256;               // int4 id 0..511
            int row = j >> 3, c16 = (j & 7) * 16;
            *(int4*)(dstb + row * FOUT + c16) = *(const int4*)(codes + row * CSTR + c16);
        }
    }

    // --- last-CTA BN finalize (replaces kC launch) ---
    __syncthreads();
    if (tid == 0) {
        __threadfence();                          // stats visible before counting
        unsigned prev = atomicAdd(&g_done, 1u);
        s_last = (prev == (unsigned)(NB_B - 1)) ? 1 : 0;
    }
    __syncthreads();
    if (s_last) {
        int o = tid;
        float sw15 = g_params[1];
        double C  = 1792.0 * (double)sw15;
        double s  = (double)g_csum[o];
        double s2 = (double)g_csum2[o];
        double mu = C * s / 65536.0;
        double m2 = C * C * s2 / 65536.0;
        double var = m2 - mu * mu;
        float tt = (float)var + 1e-5f;
        float rs = (float)(1.0 / sqrt((double)tt));
        g_bn[o] = make_float4((float)mu, rs, gamma[o], beta[o]);
        if (o < 16) g_lut[o] = __fdiv_rn((float)o, 15.0f);
    }
}

// ---------------- kernel D: thin prologue, fully unrolled latency-hiding body ----------------
__global__ void __launch_bounds__(256) kD(float* __restrict__ out) {
    __shared__ float lut[16];
    const int t = threadIdx.x;
    if (t < 16) lut[t] = g_lut[t];
    // channel group constant per thread: block stride 4096 and iter stride 256
    // are multiples of 64 -> (i4 & 63) == (t & 63)
    const int o = (t & 63) * 4;
    const float4 b0 = g_bn[o + 0], b1 = g_bn[o + 1], b2 = g_bn[o + 2], b3 = g_bn[o + 3];
    const float sw15 = g_params[1];
    __syncthreads();

    size_t base = (size_t)blockIdx.x * 4096 + t;  // char4 indices, 1024 blocks
    #pragma unroll
    for (int i = 0; i < 16; i++) {
        size_t i4 = base + (size_t)i * 256;
        char4 cc = ((const char4*)g_codes)[i4];
        float4 r;
        {
            float acc = __fmul_rn((float)((int)cc.x * 1792), sw15);
            float y = ((acc - b0.x) * b0.y) * b0.z + b0.w;
            r.x = lut[(int)rintf(fminf(fmaxf(y, 0.0f), 1.0f) * 15.0f)];
        }
        {
            float acc = __fmul_rn((float)((int)cc.y * 1792), sw15);
            float y = ((acc - b1.x) * b1.y) * b1.z + b1.w;
            r.y = lut[(int)rintf(fminf(fmaxf(y, 0.0f), 1.0f) * 15.0f)];
        }
        {
            float acc = __fmul_rn((float)((int)cc.z * 1792), sw15);
            float y = ((acc - b2.x) * b2.y) * b2.z + b2.w;
            r.z = lut[(int)rintf(fminf(fmaxf(y, 0.0f), 1.0f) * 15.0f)];
        }
        {
            float acc = __fmul_rn((float)((int)cc.w * 1792), sw15);
            float y = ((acc - b3.x) * b3.y) * b3.z + b3.w;
            r.w = lut[(int)rintf(fminf(fmaxf(y, 0.0f), 1.0f) * 15.0f)];
        }
        ((float4*)out)[i4] = r;
    }
}

// ---------------- host launch ----------------
extern "C" void kernel_launch(void* const* d_in, const int* in_sizes, int n_in,
                              void* d_out, int out_size) {
    const float* x     = (const float*)d_in[0];
    const float* w     = (const float*)d_in[1];
    const float* gamma = (const float*)d_in[2];
    const float* beta  = (const float*)d_in[3];
    float* out = (float*)d_out;

    cudaFuncSetAttribute(kB, cudaFuncAttributeMaxDynamicSharedMemorySize, SMEM_B);

    kA1<<<64, 256>>>(w);
    kA2<<<64, 256>>>(w);
    kB <<<NB_B, 256, SMEM_B>>>(x, gamma, beta);   // 2048 CTAs: (tile, half)
    kD <<<1024, 256>>>(out);                      // 1024 * 4096 char4 = 4194304
    (void)in_sizes; (void)n_in; (void)out_size;
}